// round 2
// baseline (speedup 1.0000x reference)
#include <cuda_runtime.h>
#include <math.h>

#define NUM_USERS    50000
#define NUM_ENTITIES 100000
#define NUM_RELATIONS 20
#define D            64
#define NUM_FACTORS  4
#define NUM_LAYERS   3
#define NUM_EDGES    2000000
#define NUM_INTER    2000000
#define NUM_ITEMS    30000
#define TEMPERATURE  0.2f

#define ENT_ELEMS (NUM_ENTITIES * D)   // 6,400,000
#define USR_ELEMS (NUM_USERS * D)      // 3,200,000

// ---------------- scratch (static device globals: allowed) ----------------
__device__ float g_ent[ENT_ELEMS];     // current entity embedding (l2-normed each layer)
__device__ float g_usr[USR_ELEMS];     // current user embedding
__device__ float g_neigh[ENT_ELEMS];   // KG segment-sum accumulator
__device__ float g_uagg[USR_ELEMS];    // UI segment-sum accumulator
__device__ float g_invdeg[NUM_ENTITIES];
__device__ float g_disen[NUM_FACTORS * D];

// vector reduction, no return value -> REDG path (PTX ISA 8.1+, sm_90+)
__device__ __forceinline__ void red_add_v4(float* p, float4 v) {
    asm volatile("red.global.add.v4.f32 [%0], {%1,%2,%3,%4};"
                 :: "l"(p), "f"(v.x), "f"(v.y), "f"(v.z), "f"(v.w) : "memory");
}

// ---------------- init: seed scratch + residual outputs, zero deg + accumulators ----------------
__global__ void k_init(const float* __restrict__ user_emb,
                       const float* __restrict__ entity_emb,
                       float* __restrict__ out) {
    int i = blockIdx.x * blockDim.x + threadIdx.x;
    if (i < ENT_ELEMS) {
        float v = entity_emb[i];
        g_ent[i]   = v;
        g_neigh[i] = 0.0f;
        out[i]     = v;                  // ent_res starts at entity_emb
    }
    if (i < USR_ELEMS) {
        float v = user_emb[i];
        g_usr[i]  = v;
        g_uagg[i] = 0.0f;
        out[ENT_ELEMS + i] = v;          // user_res starts at user_emb
    }
    if (i < NUM_ENTITIES) g_invdeg[i] = 0.0f;
}

// ---------------- degree count + invert ----------------
__global__ void k_degree(const int* __restrict__ edge_dst) {
    int i = blockIdx.x * blockDim.x + threadIdx.x;
    if (i < NUM_EDGES) atomicAdd(&g_invdeg[edge_dst[i]], 1.0f);
}
__global__ void k_invdeg() {
    int i = blockIdx.x * blockDim.x + threadIdx.x;
    if (i < NUM_ENTITIES) {
        float d = g_invdeg[i];
        g_invdeg[i] = (d > 0.0f) ? (1.0f / fmaxf(d, 1.0f)) : 0.0f;
    }
}

// ---------------- small: cor scalar + disen = softmax(dwa) @ rel_emb ----------------
__global__ void k_small(const float* __restrict__ rel_emb,
                        const float* __restrict__ dwa,
                        float* __restrict__ out_cor) {
    __shared__ float sw[NUM_FACTORS][NUM_RELATIONS];
    int t = threadIdx.x;
    if (t < NUM_FACTORS) {
        float m = -1e30f;
        for (int r = 0; r < NUM_RELATIONS; r++) m = fmaxf(m, dwa[t * NUM_RELATIONS + r]);
        float s = 0.0f;
        for (int r = 0; r < NUM_RELATIONS; r++) {
            float e = expf(dwa[t * NUM_RELATIONS + r] - m);
            sw[t][r] = e; s += e;
        }
        float inv = 1.0f / s;
        for (int r = 0; r < NUM_RELATIONS; r++) sw[t][r] *= inv;
    }
    if (t == 0) {
        float w[NUM_FACTORS][NUM_RELATIONS];
        for (int f = 0; f < NUM_FACTORS; f++) {
            float ss = 0.0f;
            for (int r = 0; r < NUM_RELATIONS; r++) {
                float v = dwa[f * NUM_RELATIONS + r];
                w[f][r] = v; ss += v * v;
            }
            float inv = 1.0f / fmaxf(sqrtf(ss), 1e-12f);
            for (int r = 0; r < NUM_RELATIONS; r++) w[f][r] *= inv;
        }
        float cor = 0.0f;
        for (int i = 0; i < NUM_FACTORS; i++) {
            float lg[NUM_FACTORS]; float m = -1e30f;
            for (int j = 0; j < NUM_FACTORS; j++) {
                float dot = 0.0f;
                for (int r = 0; r < NUM_RELATIONS; r++) dot += w[i][r] * w[j][r];
                lg[j] = dot / TEMPERATURE;
                m = fmaxf(m, lg[j]);
            }
            float s = 0.0f;
            for (int j = 0; j < NUM_FACTORS; j++) s += expf(lg[j] - m);
            cor -= (lg[i] - (logf(s) + m));
        }
        *out_cor = cor;
    }
    __syncthreads();
    if (t < D) {
        float acc[NUM_FACTORS] = {0.f, 0.f, 0.f, 0.f};
        for (int r = 0; r < NUM_RELATIONS; r++) {
            float rv = rel_emb[r * D + t];
            #pragma unroll
            for (int f = 0; f < NUM_FACTORS; f++) acc[f] += sw[f][r] * rv;
        }
        #pragma unroll
        for (int f = 0; f < NUM_FACTORS; f++) g_disen[f * D + t] = acc[f];
    }
}

// ---------------- KG scatter: neigh[dst] += rel_emb[rel] * ent[src] ----------------
__global__ void k_kg(const int* __restrict__ src, const int* __restrict__ dst,
                     const int* __restrict__ rel, const float* __restrict__ rel_emb) {
    long long i = (long long)blockIdx.x * blockDim.x + threadIdx.x;
    if (i >= (long long)NUM_EDGES * 16) return;
    int e = (int)(i >> 4);    // edge
    int c = ((int)i & 15) << 2;  // float offset within 64-dim row
    int s = src[e], d = dst[e], r = rel[e];
    float4 a = *reinterpret_cast<const float4*>(&g_ent[s * D + c]);
    float4 b = *reinterpret_cast<const float4*>(&rel_emb[r * D + c]);
    float4 v = make_float4(a.x * b.x, a.y * b.y, a.z * b.z, a.w * b.w);
    red_add_v4(&g_neigh[d * D + c], v);
}

// ---------------- UI scatter: uagg[user] += val * ent[item] ----------------
__global__ void k_ui(const int* __restrict__ iu, const int* __restrict__ ii,
                     const float* __restrict__ vals) {
    long long i = (long long)blockIdx.x * blockDim.x + threadIdx.x;
    if (i >= (long long)NUM_INTER * 16) return;
    int e = (int)(i >> 4);
    int c = ((int)i & 15) << 2;
    int u = iu[e], it = ii[e];
    float w = vals[e];
    float4 a = *reinterpret_cast<const float4*>(&g_ent[it * D + c]);
    float4 v = make_float4(a.x * w, a.y * w, a.z * w, a.w * w);
    red_add_v4(&g_uagg[u * D + c], v);
}

// 16-lane sum reduction (each 16-lane group handles one row)
__device__ __forceinline__ float red16(float v) {
    v += __shfl_xor_sync(0xffffffffu, v, 8, 16);
    v += __shfl_xor_sync(0xffffffffu, v, 4, 16);
    v += __shfl_xor_sync(0xffffffffu, v, 2, 16);
    v += __shfl_xor_sync(0xffffffffu, v, 1, 16);
    return v;
}

// ---------------- entity update: ent = l2norm(neigh * invdeg); ent_res += ent ----------------
// Also re-zeros g_neigh for the next layer (fuses what used to be a separate zero pass).
__global__ void k_ent_update(float* __restrict__ out_ent) {
    int gid = blockIdx.x * blockDim.x + threadIdx.x;
    if (gid >= NUM_ENTITIES * 16) return;
    int n = gid >> 4;
    int c = (gid & 15) << 2;
    float inv = g_invdeg[n];
    float4 v = *reinterpret_cast<const float4*>(&g_neigh[n * D + c]);
    *reinterpret_cast<float4*>(&g_neigh[n * D + c]) = make_float4(0.f, 0.f, 0.f, 0.f);
    v.x *= inv; v.y *= inv; v.z *= inv; v.w *= inv;
    float ss = v.x * v.x + v.y * v.y + v.z * v.z + v.w * v.w;
    ss = red16(ss);
    float r = 1.0f / fmaxf(sqrtf(ss), 1e-12f);
    float4 e = make_float4(v.x * r, v.y * r, v.z * r, v.w * r);
    *reinterpret_cast<float4*>(&g_ent[n * D + c]) = e;
    float4 acc = *reinterpret_cast<float4*>(&out_ent[n * D + c]);
    acc.x += e.x; acc.y += e.y; acc.z += e.z; acc.w += e.w;
    *reinterpret_cast<float4*>(&out_ent[n * D + c]) = acc;
}

// ---------------- user update ----------------
// score = usr @ latent^T [4]; mix = score @ disen; ua = uagg*(1+mix); usr = l2norm(ua); user_res += usr
// Also re-zeros g_uagg for the next layer.
__global__ void k_user_update(const float* __restrict__ latent, float* __restrict__ out_usr) {
    int gid = blockIdx.x * blockDim.x + threadIdx.x;
    if (gid >= NUM_USERS * 16) return;
    int u = gid >> 4;
    int c = (gid & 15) << 2;
    float4 uv = *reinterpret_cast<const float4*>(&g_usr[u * D + c]);
    float sc[NUM_FACTORS];
    #pragma unroll
    for (int f = 0; f < NUM_FACTORS; f++) {
        float4 lv = *reinterpret_cast<const float4*>(&latent[f * D + c]);
        float p = uv.x * lv.x + uv.y * lv.y + uv.z * lv.z + uv.w * lv.w;
        sc[f] = red16(p);
    }
    float4 mix = make_float4(0.f, 0.f, 0.f, 0.f);
    #pragma unroll
    for (int f = 0; f < NUM_FACTORS; f++) {
        float4 dv = *reinterpret_cast<const float4*>(&g_disen[f * D + c]);
        mix.x += sc[f] * dv.x; mix.y += sc[f] * dv.y;
        mix.z += sc[f] * dv.z; mix.w += sc[f] * dv.w;
    }
    float4 ag = *reinterpret_cast<const float4*>(&g_uagg[u * D + c]);
    *reinterpret_cast<float4*>(&g_uagg[u * D + c]) = make_float4(0.f, 0.f, 0.f, 0.f);
    float4 ua = make_float4(ag.x * (1.0f + mix.x), ag.y * (1.0f + mix.y),
                            ag.z * (1.0f + mix.z), ag.w * (1.0f + mix.w));
    float ss = ua.x * ua.x + ua.y * ua.y + ua.z * ua.z + ua.w * ua.w;
    ss = red16(ss);
    float r = 1.0f / fmaxf(sqrtf(ss), 1e-12f);
    float4 nu = make_float4(ua.x * r, ua.y * r, ua.z * r, ua.w * r);
    *reinterpret_cast<float4*>(&g_usr[u * D + c]) = nu;
    float4 acc = *reinterpret_cast<float4*>(&out_usr[u * D + c]);
    acc.x += nu.x; acc.y += nu.y; acc.z += nu.z; acc.w += nu.w;
    *reinterpret_cast<float4*>(&out_usr[u * D + c]) = acc;
}

// ---------------- launch ----------------
extern "C" void kernel_launch(void* const* d_in, const int* in_sizes, int n_in,
                              void* d_out, int out_size) {
    (void)in_sizes; (void)n_in; (void)out_size;
    const float* user_emb   = (const float*)d_in[0];
    const float* entity_emb = (const float*)d_in[1];
    const float* latent     = (const float*)d_in[2];
    const float* rel_emb    = (const float*)d_in[3];
    const float* dwa        = (const float*)d_in[4];
    const float* inter_vals = (const float*)d_in[5];
    const int*   edge_src   = (const int*)d_in[6];
    const int*   edge_dst   = (const int*)d_in[7];
    const int*   edge_rel   = (const int*)d_in[8];
    const int*   inter_user = (const int*)d_in[9];
    const int*   inter_item = (const int*)d_in[10];
    float* out = (float*)d_out;

    const int T = 256;
    k_init<<<(ENT_ELEMS + T - 1) / T, T>>>(user_emb, entity_emb, out);
    k_small<<<1, 64>>>(rel_emb, dwa, out + ENT_ELEMS + USR_ELEMS);
    k_degree<<<(NUM_EDGES + T - 1) / T, T>>>(edge_dst);
    k_invdeg<<<(NUM_ENTITIES + T - 1) / T, T>>>();

    for (int layer = 0; layer < NUM_LAYERS; layer++) {
        k_kg<<<(NUM_EDGES * 16 + T - 1) / T, T>>>(edge_src, edge_dst, edge_rel, rel_emb);
        k_ui<<<(NUM_INTER * 16 + T - 1) / T, T>>>(inter_user, inter_item, inter_vals);
        k_ent_update<<<(NUM_ENTITIES * 16 + T - 1) / T, T>>>(out);
        k_user_update<<<(NUM_USERS * 16 + T - 1) / T, T>>>(latent, out + ENT_ELEMS);
    }
}

// round 3
// speedup vs baseline: 1.0003x; 1.0003x over previous
#include <cuda_runtime.h>
#include <math.h>

#define NUM_USERS    50000
#define NUM_ENTITIES 100000
#define NUM_RELATIONS 20
#define D            64
#define NUM_FACTORS  4
#define NUM_LAYERS   3
#define NUM_EDGES    2000000
#define NUM_INTER    2000000
#define NUM_ITEMS    30000
#define TEMPERATURE  0.2f

#define ENT_ELEMS (NUM_ENTITIES * D)   // 6,400,000
#define USR_ELEMS (NUM_USERS * D)      // 3,200,000

// ---------------- scratch (static device globals: allowed) ----------------
__device__ float g_ent[ENT_ELEMS];     // current entity embedding (l2-normed each layer)
__device__ float g_usr[USR_ELEMS];     // current user embedding
__device__ float g_neigh[ENT_ELEMS];   // KG segment-sum accumulator
__device__ float g_uagg[USR_ELEMS];    // UI segment-sum accumulator
__device__ float g_invdeg[NUM_ENTITIES];
__device__ float g_disen[NUM_FACTORS * D];

// vector reduction, no return value -> REDG path (PTX ISA 8.1+, sm_90+)
__device__ __forceinline__ void red_add_v4(float* p, float4 v) {
    asm volatile("red.global.add.v4.f32 [%0], {%1,%2,%3,%4};"
                 :: "l"(p), "f"(v.x), "f"(v.y), "f"(v.z), "f"(v.w) : "memory");
}

// ---------------- init: seed scratch + residual outputs, zero deg + accumulators ----------------
__global__ void k_init(const float* __restrict__ user_emb,
                       const float* __restrict__ entity_emb,
                       float* __restrict__ out) {
    int i = blockIdx.x * blockDim.x + threadIdx.x;
    if (i < ENT_ELEMS) {
        float v = entity_emb[i];
        g_ent[i]   = v;
        g_neigh[i] = 0.0f;
        out[i]     = v;                  // ent_res starts at entity_emb
    }
    if (i < USR_ELEMS) {
        float v = user_emb[i];
        g_usr[i]  = v;
        g_uagg[i] = 0.0f;
        out[ENT_ELEMS + i] = v;          // user_res starts at user_emb
    }
    if (i < NUM_ENTITIES) g_invdeg[i] = 0.0f;
}

// ---------------- degree count + invert ----------------
__global__ void k_degree(const int* __restrict__ edge_dst) {
    int i = blockIdx.x * blockDim.x + threadIdx.x;
    if (i < NUM_EDGES) atomicAdd(&g_invdeg[edge_dst[i]], 1.0f);
}
__global__ void k_invdeg() {
    int i = blockIdx.x * blockDim.x + threadIdx.x;
    if (i < NUM_ENTITIES) {
        float d = g_invdeg[i];
        g_invdeg[i] = (d > 0.0f) ? (1.0f / fmaxf(d, 1.0f)) : 0.0f;
    }
}

// ---------------- small: cor scalar + disen = softmax(dwa) @ rel_emb ----------------
__global__ void k_small(const float* __restrict__ rel_emb,
                        const float* __restrict__ dwa,
                        float* __restrict__ out_cor) {
    __shared__ float sw[NUM_FACTORS][NUM_RELATIONS];
    int t = threadIdx.x;
    if (t < NUM_FACTORS) {
        float m = -1e30f;
        for (int r = 0; r < NUM_RELATIONS; r++) m = fmaxf(m, dwa[t * NUM_RELATIONS + r]);
        float s = 0.0f;
        for (int r = 0; r < NUM_RELATIONS; r++) {
            float e = expf(dwa[t * NUM_RELATIONS + r] - m);
            sw[t][r] = e; s += e;
        }
        float inv = 1.0f / s;
        for (int r = 0; r < NUM_RELATIONS; r++) sw[t][r] *= inv;
    }
    if (t == 0) {
        float w[NUM_FACTORS][NUM_RELATIONS];
        for (int f = 0; f < NUM_FACTORS; f++) {
            float ss = 0.0f;
            for (int r = 0; r < NUM_RELATIONS; r++) {
                float v = dwa[f * NUM_RELATIONS + r];
                w[f][r] = v; ss += v * v;
            }
            float inv = 1.0f / fmaxf(sqrtf(ss), 1e-12f);
            for (int r = 0; r < NUM_RELATIONS; r++) w[f][r] *= inv;
        }
        float cor = 0.0f;
        for (int i = 0; i < NUM_FACTORS; i++) {
            float lg[NUM_FACTORS]; float m = -1e30f;
            for (int j = 0; j < NUM_FACTORS; j++) {
                float dot = 0.0f;
                for (int r = 0; r < NUM_RELATIONS; r++) dot += w[i][r] * w[j][r];
                lg[j] = dot / TEMPERATURE;
                m = fmaxf(m, lg[j]);
            }
            float s = 0.0f;
            for (int j = 0; j < NUM_FACTORS; j++) s += expf(lg[j] - m);
            cor -= (lg[i] - (logf(s) + m));
        }
        *out_cor = cor;
    }
    __syncthreads();
    if (t < D) {
        float acc[NUM_FACTORS] = {0.f, 0.f, 0.f, 0.f};
        for (int r = 0; r < NUM_RELATIONS; r++) {
            float rv = rel_emb[r * D + t];
            #pragma unroll
            for (int f = 0; f < NUM_FACTORS; f++) acc[f] += sw[f][r] * rv;
        }
        #pragma unroll
        for (int f = 0; f < NUM_FACTORS; f++) g_disen[f * D + t] = acc[f];
    }
}

// ---------------- KG scatter: neigh[dst] += rel_emb[rel] * ent[src] ----------------
__global__ void k_kg(const int* __restrict__ src, const int* __restrict__ dst,
                     const int* __restrict__ rel, const float* __restrict__ rel_emb) {
    long long i = (long long)blockIdx.x * blockDim.x + threadIdx.x;
    if (i >= (long long)NUM_EDGES * 16) return;
    int e = (int)(i >> 4);    // edge
    int c = ((int)i & 15) << 2;  // float offset within 64-dim row
    int s = src[e], d = dst[e], r = rel[e];
    float4 a = *reinterpret_cast<const float4*>(&g_ent[s * D + c]);
    float4 b = *reinterpret_cast<const float4*>(&rel_emb[r * D + c]);
    float4 v = make_float4(a.x * b.x, a.y * b.y, a.z * b.z, a.w * b.w);
    red_add_v4(&g_neigh[d * D + c], v);
}

// ---------------- UI scatter: uagg[user] += val * ent[item] ----------------
__global__ void k_ui(const int* __restrict__ iu, const int* __restrict__ ii,
                     const float* __restrict__ vals) {
    long long i = (long long)blockIdx.x * blockDim.x + threadIdx.x;
    if (i >= (long long)NUM_INTER * 16) return;
    int e = (int)(i >> 4);
    int c = ((int)i & 15) << 2;
    int u = iu[e], it = ii[e];
    float w = vals[e];
    float4 a = *reinterpret_cast<const float4*>(&g_ent[it * D + c]);
    float4 v = make_float4(a.x * w, a.y * w, a.z * w, a.w * w);
    red_add_v4(&g_uagg[u * D + c], v);
}

// 16-lane sum reduction (each 16-lane group handles one row)
__device__ __forceinline__ float red16(float v) {
    v += __shfl_xor_sync(0xffffffffu, v, 8, 16);
    v += __shfl_xor_sync(0xffffffffu, v, 4, 16);
    v += __shfl_xor_sync(0xffffffffu, v, 2, 16);
    v += __shfl_xor_sync(0xffffffffu, v, 1, 16);
    return v;
}

// ---------------- entity update: ent = l2norm(neigh * invdeg); ent_res += ent ----------------
// Also re-zeros g_neigh for the next layer (fuses what used to be a separate zero pass).
__global__ void k_ent_update(float* __restrict__ out_ent) {
    int gid = blockIdx.x * blockDim.x + threadIdx.x;
    if (gid >= NUM_ENTITIES * 16) return;
    int n = gid >> 4;
    int c = (gid & 15) << 2;
    float inv = g_invdeg[n];
    float4 v = *reinterpret_cast<const float4*>(&g_neigh[n * D + c]);
    *reinterpret_cast<float4*>(&g_neigh[n * D + c]) = make_float4(0.f, 0.f, 0.f, 0.f);
    v.x *= inv; v.y *= inv; v.z *= inv; v.w *= inv;
    float ss = v.x * v.x + v.y * v.y + v.z * v.z + v.w * v.w;
    ss = red16(ss);
    float r = 1.0f / fmaxf(sqrtf(ss), 1e-12f);
    float4 e = make_float4(v.x * r, v.y * r, v.z * r, v.w * r);
    *reinterpret_cast<float4*>(&g_ent[n * D + c]) = e;
    float4 acc = *reinterpret_cast<float4*>(&out_ent[n * D + c]);
    acc.x += e.x; acc.y += e.y; acc.z += e.z; acc.w += e.w;
    *reinterpret_cast<float4*>(&out_ent[n * D + c]) = acc;
}

// ---------------- user update ----------------
// score = usr @ latent^T [4]; mix = score @ disen; ua = uagg*(1+mix); usr = l2norm(ua); user_res += usr
// Also re-zeros g_uagg for the next layer.
__global__ void k_user_update(const float* __restrict__ latent, float* __restrict__ out_usr) {
    int gid = blockIdx.x * blockDim.x + threadIdx.x;
    if (gid >= NUM_USERS * 16) return;
    int u = gid >> 4;
    int c = (gid & 15) << 2;
    float4 uv = *reinterpret_cast<const float4*>(&g_usr[u * D + c]);
    float sc[NUM_FACTORS];
    #pragma unroll
    for (int f = 0; f < NUM_FACTORS; f++) {
        float4 lv = *reinterpret_cast<const float4*>(&latent[f * D + c]);
        float p = uv.x * lv.x + uv.y * lv.y + uv.z * lv.z + uv.w * lv.w;
        sc[f] = red16(p);
    }
    float4 mix = make_float4(0.f, 0.f, 0.f, 0.f);
    #pragma unroll
    for (int f = 0; f < NUM_FACTORS; f++) {
        float4 dv = *reinterpret_cast<const float4*>(&g_disen[f * D + c]);
        mix.x += sc[f] * dv.x; mix.y += sc[f] * dv.y;
        mix.z += sc[f] * dv.z; mix.w += sc[f] * dv.w;
    }
    float4 ag = *reinterpret_cast<const float4*>(&g_uagg[u * D + c]);
    *reinterpret_cast<float4*>(&g_uagg[u * D + c]) = make_float4(0.f, 0.f, 0.f, 0.f);
    float4 ua = make_float4(ag.x * (1.0f + mix.x), ag.y * (1.0f + mix.y),
                            ag.z * (1.0f + mix.z), ag.w * (1.0f + mix.w));
    float ss = ua.x * ua.x + ua.y * ua.y + ua.z * ua.z + ua.w * ua.w;
    ss = red16(ss);
    float r = 1.0f / fmaxf(sqrtf(ss), 1e-12f);
    float4 nu = make_float4(ua.x * r, ua.y * r, ua.z * r, ua.w * r);
    *reinterpret_cast<float4*>(&g_usr[u * D + c]) = nu;
    float4 acc = *reinterpret_cast<float4*>(&out_usr[u * D + c]);
    acc.x += nu.x; acc.y += nu.y; acc.z += nu.z; acc.w += nu.w;
    *reinterpret_cast<float4*>(&out_usr[u * D + c]) = acc;
}

// ---------------- launch ----------------
extern "C" void kernel_launch(void* const* d_in, const int* in_sizes, int n_in,
                              void* d_out, int out_size) {
    (void)in_sizes; (void)n_in; (void)out_size;
    const float* user_emb   = (const float*)d_in[0];
    const float* entity_emb = (const float*)d_in[1];
    const float* latent     = (const float*)d_in[2];
    const float* rel_emb    = (const float*)d_in[3];
    const float* dwa        = (const float*)d_in[4];
    const float* inter_vals = (const float*)d_in[5];
    const int*   edge_src   = (const int*)d_in[6];
    const int*   edge_dst   = (const int*)d_in[7];
    const int*   edge_rel   = (const int*)d_in[8];
    const int*   inter_user = (const int*)d_in[9];
    const int*   inter_item = (const int*)d_in[10];
    float* out = (float*)d_out;

    const int T = 256;
    k_init<<<(ENT_ELEMS + T - 1) / T, T>>>(user_emb, entity_emb, out);
    k_small<<<1, 64>>>(rel_emb, dwa, out + ENT_ELEMS + USR_ELEMS);
    k_degree<<<(NUM_EDGES + T - 1) / T, T>>>(edge_dst);
    k_invdeg<<<(NUM_ENTITIES + T - 1) / T, T>>>();

    for (int layer = 0; layer < NUM_LAYERS; layer++) {
        k_kg<<<(NUM_EDGES * 16 + T - 1) / T, T>>>(edge_src, edge_dst, edge_rel, rel_emb);
        k_ui<<<(NUM_INTER * 16 + T - 1) / T, T>>>(inter_user, inter_item, inter_vals);
        k_ent_update<<<(NUM_ENTITIES * 16 + T - 1) / T, T>>>(out);
        k_user_update<<<(NUM_USERS * 16 + T - 1) / T, T>>>(latent, out + ENT_ELEMS);
    }
}

// round 4
// speedup vs baseline: 1.0017x; 1.0014x over previous
#include <cuda_runtime.h>
#include <math.h>

#define NUM_USERS    50000
#define NUM_ENTITIES 100000
#define NUM_RELATIONS 20
#define D            64
#define NUM_FACTORS  4
#define NUM_LAYERS   3
#define NUM_EDGES    2000000
#define NUM_INTER    2000000
#define NUM_ITEMS    30000
#define TEMPERATURE  0.2f

#define ENT_ELEMS (NUM_ENTITIES * D)   // 6,400,000
#define USR_ELEMS (NUM_USERS * D)      // 3,200,000

// ---------------- scratch (static device globals: allowed) ----------------
__device__ float g_ent[ENT_ELEMS];     // current entity embedding (l2-normed each layer)
__device__ float g_usr[USR_ELEMS];     // current user embedding
__device__ float g_neigh[ENT_ELEMS];   // KG segment-sum accumulator
__device__ float g_uagg[USR_ELEMS];    // UI segment-sum accumulator
__device__ float g_invdeg[NUM_ENTITIES];
__device__ float g_disen[NUM_FACTORS * D];

// vector reduction, no return value -> REDG path (PTX ISA 8.1+, sm_90+)
__device__ __forceinline__ void red_add_v4(float* p, float4 v) {
    asm volatile("red.global.add.v4.f32 [%0], {%1,%2,%3,%4};"
                 :: "l"(p), "f"(v.x), "f"(v.y), "f"(v.z), "f"(v.w) : "memory");
}

// ---------------- init: seed scratch + residual outputs, zero deg + accumulators ----------------
__global__ void k_init(const float* __restrict__ user_emb,
                       const float* __restrict__ entity_emb,
                       float* __restrict__ out) {
    int i = blockIdx.x * blockDim.x + threadIdx.x;
    if (i < ENT_ELEMS) {
        float v = entity_emb[i];
        g_ent[i]   = v;
        g_neigh[i] = 0.0f;
        out[i]     = v;                  // ent_res starts at entity_emb
    }
    if (i < USR_ELEMS) {
        float v = user_emb[i];
        g_usr[i]  = v;
        g_uagg[i] = 0.0f;
        out[ENT_ELEMS + i] = v;          // user_res starts at user_emb
    }
    if (i < NUM_ENTITIES) g_invdeg[i] = 0.0f;
}

// ---------------- degree count + invert ----------------
__global__ void k_degree(const int* __restrict__ edge_dst) {
    int i = blockIdx.x * blockDim.x + threadIdx.x;
    if (i < NUM_EDGES) atomicAdd(&g_invdeg[edge_dst[i]], 1.0f);
}
__global__ void k_invdeg() {
    int i = blockIdx.x * blockDim.x + threadIdx.x;
    if (i < NUM_ENTITIES) {
        float d = g_invdeg[i];
        g_invdeg[i] = (d > 0.0f) ? (1.0f / fmaxf(d, 1.0f)) : 0.0f;
    }
}

// ---------------- small: cor scalar + disen = softmax(dwa) @ rel_emb ----------------
__global__ void k_small(const float* __restrict__ rel_emb,
                        const float* __restrict__ dwa,
                        float* __restrict__ out_cor) {
    __shared__ float sw[NUM_FACTORS][NUM_RELATIONS];
    int t = threadIdx.x;
    if (t < NUM_FACTORS) {
        float m = -1e30f;
        for (int r = 0; r < NUM_RELATIONS; r++) m = fmaxf(m, dwa[t * NUM_RELATIONS + r]);
        float s = 0.0f;
        for (int r = 0; r < NUM_RELATIONS; r++) {
            float e = expf(dwa[t * NUM_RELATIONS + r] - m);
            sw[t][r] = e; s += e;
        }
        float inv = 1.0f / s;
        for (int r = 0; r < NUM_RELATIONS; r++) sw[t][r] *= inv;
    }
    if (t == 0) {
        float w[NUM_FACTORS][NUM_RELATIONS];
        for (int f = 0; f < NUM_FACTORS; f++) {
            float ss = 0.0f;
            for (int r = 0; r < NUM_RELATIONS; r++) {
                float v = dwa[f * NUM_RELATIONS + r];
                w[f][r] = v; ss += v * v;
            }
            float inv = 1.0f / fmaxf(sqrtf(ss), 1e-12f);
            for (int r = 0; r < NUM_RELATIONS; r++) w[f][r] *= inv;
        }
        float cor = 0.0f;
        for (int i = 0; i < NUM_FACTORS; i++) {
            float lg[NUM_FACTORS]; float m = -1e30f;
            for (int j = 0; j < NUM_FACTORS; j++) {
                float dot = 0.0f;
                for (int r = 0; r < NUM_RELATIONS; r++) dot += w[i][r] * w[j][r];
                lg[j] = dot / TEMPERATURE;
                m = fmaxf(m, lg[j]);
            }
            float s = 0.0f;
            for (int j = 0; j < NUM_FACTORS; j++) s += expf(lg[j] - m);
            cor -= (lg[i] - (logf(s) + m));
        }
        *out_cor = cor;
    }
    __syncthreads();
    if (t < D) {
        float acc[NUM_FACTORS] = {0.f, 0.f, 0.f, 0.f};
        for (int r = 0; r < NUM_RELATIONS; r++) {
            float rv = rel_emb[r * D + t];
            #pragma unroll
            for (int f = 0; f < NUM_FACTORS; f++) acc[f] += sw[f][r] * rv;
        }
        #pragma unroll
        for (int f = 0; f < NUM_FACTORS; f++) g_disen[f * D + t] = acc[f];
    }
}

// ---------------- KG scatter: neigh[dst] += rel_emb[rel] * ent[src] ----------------
__global__ void k_kg(const int* __restrict__ src, const int* __restrict__ dst,
                     const int* __restrict__ rel, const float* __restrict__ rel_emb) {
    long long i = (long long)blockIdx.x * blockDim.x + threadIdx.x;
    if (i >= (long long)NUM_EDGES * 16) return;
    int e = (int)(i >> 4);    // edge
    int c = ((int)i & 15) << 2;  // float offset within 64-dim row
    int s = src[e], d = dst[e], r = rel[e];
    float4 a = *reinterpret_cast<const float4*>(&g_ent[s * D + c]);
    float4 b = *reinterpret_cast<const float4*>(&rel_emb[r * D + c]);
    float4 v = make_float4(a.x * b.x, a.y * b.y, a.z * b.z, a.w * b.w);
    red_add_v4(&g_neigh[d * D + c], v);
}

// ---------------- UI scatter: uagg[user] += val * ent[item] ----------------
__global__ void k_ui(const int* __restrict__ iu, const int* __restrict__ ii,
                     const float* __restrict__ vals) {
    long long i = (long long)blockIdx.x * blockDim.x + threadIdx.x;
    if (i >= (long long)NUM_INTER * 16) return;
    int e = (int)(i >> 4);
    int c = ((int)i & 15) << 2;
    int u = iu[e], it = ii[e];
    float w = vals[e];
    float4 a = *reinterpret_cast<const float4*>(&g_ent[it * D + c]);
    float4 v = make_float4(a.x * w, a.y * w, a.z * w, a.w * w);
    red_add_v4(&g_uagg[u * D + c], v);
}

// 16-lane sum reduction (each 16-lane group handles one row)
__device__ __forceinline__ float red16(float v) {
    v += __shfl_xor_sync(0xffffffffu, v, 8, 16);
    v += __shfl_xor_sync(0xffffffffu, v, 4, 16);
    v += __shfl_xor_sync(0xffffffffu, v, 2, 16);
    v += __shfl_xor_sync(0xffffffffu, v, 1, 16);
    return v;
}

// ---------------- entity update: ent = l2norm(neigh * invdeg); ent_res += ent ----------------
// Also re-zeros g_neigh for the next layer (fuses what used to be a separate zero pass).
__global__ void k_ent_update(float* __restrict__ out_ent) {
    int gid = blockIdx.x * blockDim.x + threadIdx.x;
    if (gid >= NUM_ENTITIES * 16) return;
    int n = gid >> 4;
    int c = (gid & 15) << 2;
    float inv = g_invdeg[n];
    float4 v = *reinterpret_cast<const float4*>(&g_neigh[n * D + c]);
    *reinterpret_cast<float4*>(&g_neigh[n * D + c]) = make_float4(0.f, 0.f, 0.f, 0.f);
    v.x *= inv; v.y *= inv; v.z *= inv; v.w *= inv;
    float ss = v.x * v.x + v.y * v.y + v.z * v.z + v.w * v.w;
    ss = red16(ss);
    float r = 1.0f / fmaxf(sqrtf(ss), 1e-12f);
    float4 e = make_float4(v.x * r, v.y * r, v.z * r, v.w * r);
    *reinterpret_cast<float4*>(&g_ent[n * D + c]) = e;
    float4 acc = *reinterpret_cast<float4*>(&out_ent[n * D + c]);
    acc.x += e.x; acc.y += e.y; acc.z += e.z; acc.w += e.w;
    *reinterpret_cast<float4*>(&out_ent[n * D + c]) = acc;
}

// ---------------- user update ----------------
// score = usr @ latent^T [4]; mix = score @ disen; ua = uagg*(1+mix); usr = l2norm(ua); user_res += usr
// Also re-zeros g_uagg for the next layer.
__global__ void k_user_update(const float* __restrict__ latent, float* __restrict__ out_usr) {
    int gid = blockIdx.x * blockDim.x + threadIdx.x;
    if (gid >= NUM_USERS * 16) return;
    int u = gid >> 4;
    int c = (gid & 15) << 2;
    float4 uv = *reinterpret_cast<const float4*>(&g_usr[u * D + c]);
    float sc[NUM_FACTORS];
    #pragma unroll
    for (int f = 0; f < NUM_FACTORS; f++) {
        float4 lv = *reinterpret_cast<const float4*>(&latent[f * D + c]);
        float p = uv.x * lv.x + uv.y * lv.y + uv.z * lv.z + uv.w * lv.w;
        sc[f] = red16(p);
    }
    float4 mix = make_float4(0.f, 0.f, 0.f, 0.f);
    #pragma unroll
    for (int f = 0; f < NUM_FACTORS; f++) {
        float4 dv = *reinterpret_cast<const float4*>(&g_disen[f * D + c]);
        mix.x += sc[f] * dv.x; mix.y += sc[f] * dv.y;
        mix.z += sc[f] * dv.z; mix.w += sc[f] * dv.w;
    }
    float4 ag = *reinterpret_cast<const float4*>(&g_uagg[u * D + c]);
    *reinterpret_cast<float4*>(&g_uagg[u * D + c]) = make_float4(0.f, 0.f, 0.f, 0.f);
    float4 ua = make_float4(ag.x * (1.0f + mix.x), ag.y * (1.0f + mix.y),
                            ag.z * (1.0f + mix.z), ag.w * (1.0f + mix.w));
    float ss = ua.x * ua.x + ua.y * ua.y + ua.z * ua.z + ua.w * ua.w;
    ss = red16(ss);
    float r = 1.0f / fmaxf(sqrtf(ss), 1e-12f);
    float4 nu = make_float4(ua.x * r, ua.y * r, ua.z * r, ua.w * r);
    *reinterpret_cast<float4*>(&g_usr[u * D + c]) = nu;
    float4 acc = *reinterpret_cast<float4*>(&out_usr[u * D + c]);
    acc.x += nu.x; acc.y += nu.y; acc.z += nu.z; acc.w += nu.w;
    *reinterpret_cast<float4*>(&out_usr[u * D + c]) = acc;
}

// ---------------- launch ----------------
extern "C" void kernel_launch(void* const* d_in, const int* in_sizes, int n_in,
                              void* d_out, int out_size) {
    (void)in_sizes; (void)n_in; (void)out_size;
    const float* user_emb   = (const float*)d_in[0];
    const float* entity_emb = (const float*)d_in[1];
    const float* latent     = (const float*)d_in[2];
    const float* rel_emb    = (const float*)d_in[3];
    const float* dwa        = (const float*)d_in[4];
    const float* inter_vals = (const float*)d_in[5];
    const int*   edge_src   = (const int*)d_in[6];
    const int*   edge_dst   = (const int*)d_in[7];
    const int*   edge_rel   = (const int*)d_in[8];
    const int*   inter_user = (const int*)d_in[9];
    const int*   inter_item = (const int*)d_in[10];
    float* out = (float*)d_out;

    const int T = 256;
    k_init<<<(ENT_ELEMS + T - 1) / T, T>>>(user_emb, entity_emb, out);
    k_small<<<1, 64>>>(rel_emb, dwa, out + ENT_ELEMS + USR_ELEMS);
    k_degree<<<(NUM_EDGES + T - 1) / T, T>>>(edge_dst);
    k_invdeg<<<(NUM_ENTITIES + T - 1) / T, T>>>();

    for (int layer = 0; layer < NUM_LAYERS; layer++) {
        k_kg<<<(NUM_EDGES * 16 + T - 1) / T, T>>>(edge_src, edge_dst, edge_rel, rel_emb);
        k_ui<<<(NUM_INTER * 16 + T - 1) / T, T>>>(inter_user, inter_item, inter_vals);
        k_ent_update<<<(NUM_ENTITIES * 16 + T - 1) / T, T>>>(out);
        k_user_update<<<(NUM_USERS * 16 + T - 1) / T, T>>>(latent, out + ENT_ELEMS);
    }
}